// round 2
// baseline (speedup 1.0000x reference)
#include <cuda_runtime.h>
#include <cuda_bf16.h>

// Problem constants
#define BATCH   2
#define SEQ     2048
#define CDIM    768
#define HEADS   12
#define HDIM    64
#define QKV_N   (3 * CDIM)          // 2304
#define MROWS   (BATCH * SEQ)       // 4096
#define SCALE   0.125f              // 1/sqrt(64)

// Scratch (static device allocations are allowed)
__device__ float g_q[BATCH * HEADS * SEQ * HDIM];   // [b,h,n,d]
__device__ float g_k[BATCH * HEADS * SEQ * HDIM];
__device__ float g_v[BATCH * HEADS * SEQ * HDIM];
__device__ float g_ctx[BATCH * SEQ * CDIM];         // [b,n,h*64+d]

// ---------------------------------------------------------------------------
// Kernel 1: QKV projection.  qkv[m,n] = sum_k x[m,k] * w_qkv[n,k]
// 64x64 output tile per CTA, 256 threads, 4x4 micro-tile per thread.
// Epilogue scatters directly into g_q/g_k/g_v in [b,h,n,d] layout.
// ---------------------------------------------------------------------------
__global__ __launch_bounds__(256) void qkv_kernel(const float* __restrict__ x,
                                                  const float* __restrict__ w)
{
    __shared__ float As[64][33];
    __shared__ float Bs[64][33];

    const int m0 = blockIdx.y * 64;
    const int n0 = blockIdx.x * 64;
    const int tid = threadIdx.x;
    const int tx = tid & 15;
    const int ty = tid >> 4;
    const int lrow = tid >> 3;           // 0..31
    const int lc4  = (tid & 7) << 2;     // 0,4,...,28

    float acc[4][4] = {};

    for (int k0 = 0; k0 < CDIM; k0 += 32) {
#pragma unroll
        for (int rr = 0; rr < 64; rr += 32) {
            float4 va = *reinterpret_cast<const float4*>(x + (size_t)(m0 + lrow + rr) * CDIM + k0 + lc4);
            As[lrow + rr][lc4 + 0] = va.x;
            As[lrow + rr][lc4 + 1] = va.y;
            As[lrow + rr][lc4 + 2] = va.z;
            As[lrow + rr][lc4 + 3] = va.w;
            float4 vb = *reinterpret_cast<const float4*>(w + (size_t)(n0 + lrow + rr) * CDIM + k0 + lc4);
            Bs[lrow + rr][lc4 + 0] = vb.x;
            Bs[lrow + rr][lc4 + 1] = vb.y;
            Bs[lrow + rr][lc4 + 2] = vb.z;
            Bs[lrow + rr][lc4 + 3] = vb.w;
        }
        __syncthreads();
#pragma unroll
        for (int kk = 0; kk < 32; kk++) {
            float a[4], b[4];
#pragma unroll
            for (int i = 0; i < 4; i++) a[i] = As[ty * 4 + i][kk];
#pragma unroll
            for (int j = 0; j < 4; j++) b[j] = Bs[tx * 4 + j][kk];
#pragma unroll
            for (int i = 0; i < 4; i++)
#pragma unroll
                for (int j = 0; j < 4; j++)
                    acc[i][j] = fmaf(a[i], b[j], acc[i][j]);
        }
        __syncthreads();
    }

    // Scatter: n-tile (64 wide) maps to exactly one (s, h) pair.
    const int s   = n0 / CDIM;            // 0=q, 1=k, 2=v
    const int rem = n0 % CDIM;
    const int h   = rem >> 6;             // head
    float* dst = (s == 0) ? g_q : ((s == 1) ? g_k : g_v);
    const int b   = m0 >> 11;             // m0 / 2048
    const int nr0 = m0 & 2047;
    float* base = dst + ((size_t)(b * HEADS + h) * SEQ + nr0) * HDIM;

#pragma unroll
    for (int i = 0; i < 4; i++)
#pragma unroll
        for (int j = 0; j < 4; j++)
            base[(size_t)(ty * 4 + i) * HDIM + tx * 4 + j] = acc[i][j];
}

// ---------------------------------------------------------------------------
// Kernel 2: flash attention.  One CTA per (b*h, 64-row q tile).
// K and V share one smem buffer (V loaded after S is computed).
// ---------------------------------------------------------------------------
__global__ __launch_bounds__(256) void attn_kernel()
{
    extern __shared__ float sm[];
    float (*Qs)[65]  = reinterpret_cast<float(*)[65]>(sm);
    float (*KVs)[65] = reinterpret_cast<float(*)[65]>(sm + 64 * 65);
    float (*Ps)[65]  = reinterpret_cast<float(*)[65]>(sm + 2 * 64 * 65);
    float* row_m = sm + 3 * 64 * 65;
    float* row_l = row_m + 64;
    float* row_c = row_l + 64;

    const int q0 = blockIdx.x * 64;
    const int bh = blockIdx.y;                       // 0..23
    const float* Q = g_q + (size_t)bh * SEQ * HDIM;
    const float* K = g_k + (size_t)bh * SEQ * HDIM;
    const float* V = g_v + (size_t)bh * SEQ * HDIM;

    const int tid  = threadIdx.x;
    const int tx   = tid & 15;
    const int ty   = tid >> 4;
    const int lr   = tid >> 4;                       // 0..15
    const int lcol = (tid & 15) << 2;                // 0..60

    // Load Q tile
#pragma unroll
    for (int rr = 0; rr < 64; rr += 16) {
        float4 v4 = *reinterpret_cast<const float4*>(Q + (size_t)(q0 + lr + rr) * HDIM + lcol);
        Qs[lr + rr][lcol + 0] = v4.x;
        Qs[lr + rr][lcol + 1] = v4.y;
        Qs[lr + rr][lcol + 2] = v4.z;
        Qs[lr + rr][lcol + 3] = v4.w;
    }
    if (tid < 64) { row_m[tid] = -1e30f; row_l[tid] = 0.0f; }

    float oacc[4][4] = {};
    __syncthreads();

    for (int kv0 = 0; kv0 < SEQ; kv0 += 64) {
        // Load K tile
#pragma unroll
        for (int rr = 0; rr < 64; rr += 16) {
            float4 v4 = *reinterpret_cast<const float4*>(K + (size_t)(kv0 + lr + rr) * HDIM + lcol);
            KVs[lr + rr][lcol + 0] = v4.x;
            KVs[lr + rr][lcol + 1] = v4.y;
            KVs[lr + rr][lcol + 2] = v4.z;
            KVs[lr + rr][lcol + 3] = v4.w;
        }
        __syncthreads();

        // S = (Q K^T) * scale  -> Ps
        float sacc[4][4] = {};
#pragma unroll
        for (int kk = 0; kk < 64; kk++) {
            float a[4], b[4];
#pragma unroll
            for (int i = 0; i < 4; i++) a[i] = Qs[ty * 4 + i][kk];
#pragma unroll
            for (int j = 0; j < 4; j++) b[j] = KVs[tx * 4 + j][kk];
#pragma unroll
            for (int i = 0; i < 4; i++)
#pragma unroll
                for (int j = 0; j < 4; j++)
                    sacc[i][j] = fmaf(a[i], b[j], sacc[i][j]);
        }
#pragma unroll
        for (int i = 0; i < 4; i++)
#pragma unroll
            for (int j = 0; j < 4; j++)
                Ps[ty * 4 + i][tx * 4 + j] = sacc[i][j] * SCALE;
        __syncthreads();

        // Load V tile (overwrite K) + online softmax on Ps (threads < 64)
#pragma unroll
        for (int rr = 0; rr < 64; rr += 16) {
            float4 v4 = *reinterpret_cast<const float4*>(V + (size_t)(kv0 + lr + rr) * HDIM + lcol);
            KVs[lr + rr][lcol + 0] = v4.x;
            KVs[lr + rr][lcol + 1] = v4.y;
            KVs[lr + rr][lcol + 2] = v4.z;
            KVs[lr + rr][lcol + 3] = v4.w;
        }
        if (tid < 64) {
            const int r = tid;
            float m_old = row_m[r];
            float tm = m_old;
#pragma unroll 16
            for (int j = 0; j < 64; j++) tm = fmaxf(tm, Ps[r][j]);
            float corr = __expf(m_old - tm);
            float ls = 0.0f;
#pragma unroll 16
            for (int j = 0; j < 64; j++) {
                float p = __expf(Ps[r][j] - tm);
                Ps[r][j] = p;
                ls += p;
            }
            row_m[r] = tm;
            row_l[r] = row_l[r] * corr + ls;
            row_c[r] = corr;
        }
        __syncthreads();

        // Rescale accumulator, then O += P V
        float c[4];
#pragma unroll
        for (int i = 0; i < 4; i++) c[i] = row_c[ty * 4 + i];
#pragma unroll
        for (int i = 0; i < 4; i++)
#pragma unroll
            for (int j = 0; j < 4; j++)
                oacc[i][j] *= c[i];

#pragma unroll
        for (int kk = 0; kk < 64; kk++) {
            float p[4], v[4];
#pragma unroll
            for (int i = 0; i < 4; i++) p[i] = Ps[ty * 4 + i][kk];
#pragma unroll
            for (int j = 0; j < 4; j++) v[j] = KVs[kk][tx * 4 + j];
#pragma unroll
            for (int i = 0; i < 4; i++)
#pragma unroll
                for (int j = 0; j < 4; j++)
                    oacc[i][j] = fmaf(p[i], v[j], oacc[i][j]);
        }
        __syncthreads();
    }

    // Epilogue: normalize and write ctx [b, n, h*64+d]
    const int b = bh / HEADS;
    const int h = bh % HEADS;
    float inv[4];
#pragma unroll
    for (int i = 0; i < 4; i++) inv[i] = 1.0f / row_l[ty * 4 + i];
    float* outp = g_ctx + ((size_t)(b * SEQ + q0)) * CDIM + h * HDIM;
#pragma unroll
    for (int i = 0; i < 4; i++)
#pragma unroll
        for (int j = 0; j < 4; j++)
            outp[(size_t)(ty * 4 + i) * CDIM + tx * 4 + j] = oacc[i][j] * inv[i];
}

// ---------------------------------------------------------------------------
// Kernel 3: output projection.  out[m,n] = sum_k ctx[m,k] * w_proj[n,k] + b[n]
// ---------------------------------------------------------------------------
__global__ __launch_bounds__(256) void proj_kernel(const float* __restrict__ w,
                                                   const float* __restrict__ bias,
                                                   float* __restrict__ out)
{
    __shared__ float As[64][33];
    __shared__ float Bs[64][33];

    const int m0 = blockIdx.y * 64;
    const int n0 = blockIdx.x * 64;
    const int tid = threadIdx.x;
    const int tx = tid & 15;
    const int ty = tid >> 4;
    const int lrow = tid >> 3;
    const int lc4  = (tid & 7) << 2;

    float acc[4][4] = {};

    for (int k0 = 0; k0 < CDIM; k0 += 32) {
#pragma unroll
        for (int rr = 0; rr < 64; rr += 32) {
            float4 va = *reinterpret_cast<const float4*>(g_ctx + (size_t)(m0 + lrow + rr) * CDIM + k0 + lc4);
            As[lrow + rr][lc4 + 0] = va.x;
            As[lrow + rr][lc4 + 1] = va.y;
            As[lrow + rr][lc4 + 2] = va.z;
            As[lrow + rr][lc4 + 3] = va.w;
            float4 vb = *reinterpret_cast<const float4*>(w + (size_t)(n0 + lrow + rr) * CDIM + k0 + lc4);
            Bs[lrow + rr][lc4 + 0] = vb.x;
            Bs[lrow + rr][lc4 + 1] = vb.y;
            Bs[lrow + rr][lc4 + 2] = vb.z;
            Bs[lrow + rr][lc4 + 3] = vb.w;
        }
        __syncthreads();
#pragma unroll
        for (int kk = 0; kk < 32; kk++) {
            float a[4], b[4];
#pragma unroll
            for (int i = 0; i < 4; i++) a[i] = As[ty * 4 + i][kk];
#pragma unroll
            for (int j = 0; j < 4; j++) b[j] = Bs[tx * 4 + j][kk];
#pragma unroll
            for (int i = 0; i < 4; i++)
#pragma unroll
                for (int j = 0; j < 4; j++)
                    acc[i][j] = fmaf(a[i], b[j], acc[i][j]);
        }
        __syncthreads();
    }

#pragma unroll
    for (int i = 0; i < 4; i++)
#pragma unroll
        for (int j = 0; j < 4; j++)
            out[(size_t)(m0 + ty * 4 + i) * CDIM + n0 + tx * 4 + j] =
                acc[i][j] + bias[n0 + tx * 4 + j];
}

// ---------------------------------------------------------------------------
// Launch
// ---------------------------------------------------------------------------
extern "C" void kernel_launch(void* const* d_in, const int* in_sizes, int n_in,
                              void* d_out, int out_size)
{
    const float* x      = (const float*)d_in[0];   // [2,2048,768]
    const float* w_qkv  = (const float*)d_in[1];   // [2304,768]
    const float* w_proj = (const float*)d_in[2];   // [768,768]
    const float* b_proj = (const float*)d_in[3];   // [768]
    float* out = (float*)d_out;                    // [2,2048,768]

    (void)in_sizes; (void)n_in; (void)out_size;

    // 1) QKV projection: grid (N-tiles=36, M-tiles=64)
    qkv_kernel<<<dim3(QKV_N / 64, MROWS / 64), 256>>>(x, w_qkv);

    // 2) Attention: grid (q-tiles=32, b*h=24); 50,688 B dynamic smem
    const int attn_smem = (3 * 64 * 65 + 3 * 64) * (int)sizeof(float);
    cudaFuncSetAttribute(attn_kernel, cudaFuncAttributeMaxDynamicSharedMemorySize, attn_smem);
    attn_kernel<<<dim3(SEQ / 64, BATCH * HEADS), 256, attn_smem>>>();

    // 3) Output projection: grid (N-tiles=12, M-tiles=64)
    proj_kernel<<<dim3(CDIM / 64, MROWS / 64), 256>>>(w_proj, b_proj, out);
}

// round 5
// speedup vs baseline: 2.6200x; 2.6200x over previous
#include <cuda_runtime.h>
#include <cuda_bf16.h>
#include <cstdint>

#define BATCH   2
#define SEQ     2048
#define CDIM    768
#define HEADS   12
#define HDIM    64
#define QKV_N   2304
#define MROWS   4096
#define BH      24
#define SCALEF  0.125f

// ---------------------------------------------------------------------------
// Scratch
// ---------------------------------------------------------------------------
__device__ __nv_bfloat16 g_x_hi[MROWS * CDIM];
__device__ __nv_bfloat16 g_x_lo[MROWS * CDIM];
__device__ __nv_bfloat16 g_wqkv_hi[QKV_N * CDIM];
__device__ __nv_bfloat16 g_wqkv_lo[QKV_N * CDIM];
__device__ __nv_bfloat16 g_wproj_hi[CDIM * CDIM];
__device__ __nv_bfloat16 g_wproj_lo[CDIM * CDIM];
__device__ __nv_bfloat16 g_q_hi[BH * SEQ * HDIM];    // [b,h,n,d], pre-scaled by 1/8
__device__ __nv_bfloat16 g_q_lo[BH * SEQ * HDIM];
__device__ __nv_bfloat16 g_k_hi[BH * SEQ * HDIM];
__device__ __nv_bfloat16 g_k_lo[BH * SEQ * HDIM];
__device__ __nv_bfloat16 g_vt_hi[BH * HDIM * SEQ];   // [b,h,d,n]
__device__ __nv_bfloat16 g_vt_lo[BH * HDIM * SEQ];
__device__ __nv_bfloat16 g_ctx_hi[MROWS * CDIM];
__device__ __nv_bfloat16 g_ctx_lo[MROWS * CDIM];

// ---------------------------------------------------------------------------
// Helpers (all plain sm_80-era PTX: valid on compute_100 without 'a')
// ---------------------------------------------------------------------------
__device__ __forceinline__ uint32_t smem_u32(const void* p) {
    uint32_t a;
    asm("{ .reg .u64 t; cvta.to.shared.u64 t, %1; cvt.u32.u64 %0, t; }" : "=r"(a) : "l"(p));
    return a;
}
__device__ __forceinline__ void cp16(uint32_t dst, const void* src) {
    asm volatile("cp.async.cg.shared.global [%0], [%1], 16;" :: "r"(dst), "l"(src));
}
__device__ __forceinline__ void cp_commit() { asm volatile("cp.async.commit_group;"); }
template <int N> __device__ __forceinline__ void cp_wait() {
    asm volatile("cp.async.wait_group %0;" :: "n"(N));
}
__device__ __forceinline__ void ldsm4(uint32_t a, uint32_t& r0, uint32_t& r1, uint32_t& r2, uint32_t& r3) {
    asm volatile("ldmatrix.sync.aligned.m8n8.x4.shared.b16 {%0,%1,%2,%3}, [%4];"
                 : "=r"(r0), "=r"(r1), "=r"(r2), "=r"(r3) : "r"(a));
}
__device__ __forceinline__ void mma16816(float* c, const uint32_t* a, const uint32_t* b) {
    asm volatile("mma.sync.aligned.m16n8k16.row.col.f32.bf16.bf16.f32 "
                 "{%0,%1,%2,%3}, {%4,%5,%6,%7}, {%8,%9}, {%0,%1,%2,%3};"
                 : "+f"(c[0]), "+f"(c[1]), "+f"(c[2]), "+f"(c[3])
                 : "r"(a[0]), "r"(a[1]), "r"(a[2]), "r"(a[3]), "r"(b[0]), "r"(b[1]));
}
__device__ __forceinline__ void split2(float x, float y, uint32_t& hi, uint32_t& lo) {
    __nv_bfloat16 hx = __float2bfloat16_rn(x), hy = __float2bfloat16_rn(y);
    __nv_bfloat162 H; H.x = hx; H.y = hy;
    __nv_bfloat162 L;
    L.x = __float2bfloat16_rn(x - __bfloat162float(hx));
    L.y = __float2bfloat16_rn(y - __bfloat162float(hy));
    hi = *reinterpret_cast<uint32_t*>(&H);
    lo = *reinterpret_cast<uint32_t*>(&L);
}

// ---------------------------------------------------------------------------
// Convert fp32 -> split bf16
// ---------------------------------------------------------------------------
__global__ void convert_split(const float* __restrict__ src,
                              __nv_bfloat16* __restrict__ hi,
                              __nv_bfloat16* __restrict__ lo, int n)
{
    int i = blockIdx.x * blockDim.x + threadIdx.x;
    for (; i < n; i += gridDim.x * blockDim.x) {
        float v = src[i];
        __nv_bfloat16 h = __float2bfloat16_rn(v);
        hi[i] = h;
        lo[i] = __float2bfloat16_rn(v - __bfloat162float(h));
    }
}

// ---------------------------------------------------------------------------
// GEMM core: C(128x128) = (Ahi+Alo)(Bhi+Blo)^T over K=768. 256 threads.
// smem stage: [Ahi 10240][Alo 10240][Bhi 10240][Blo 10240], rows padded to 80B.
// ---------------------------------------------------------------------------
#define GSTAGE   40960
#define G_ALO    10240
#define G_BHI    20480
#define G_BLO    30720
#define GEMM_SMEM (2 * GSTAGE)

__device__ __forceinline__ void gemm_load_stage(
    uint32_t sb, const __nv_bfloat16* Ahi, const __nv_bfloat16* Alo,
    const __nv_bfloat16* Bhi, const __nv_bfloat16* Blo,
    int m0, int n0, int k0, int tid)
{
    const int row = tid >> 1;
    const int cb  = (tid & 1) * 32;                 // byte offset in 64B row
    const size_t ga = (size_t)(m0 + row) * CDIM + k0;
    const size_t gb = (size_t)(n0 + row) * CDIM + k0;
    const uint32_t so = (uint32_t)row * 80 + cb;
    cp16(sb + so,               (const char*)(Ahi + ga) + cb);
    cp16(sb + so + 16,          (const char*)(Ahi + ga) + cb + 16);
    cp16(sb + G_ALO + so,       (const char*)(Alo + ga) + cb);
    cp16(sb + G_ALO + so + 16,  (const char*)(Alo + ga) + cb + 16);
    cp16(sb + G_BHI + so,       (const char*)(Bhi + gb) + cb);
    cp16(sb + G_BHI + so + 16,  (const char*)(Bhi + gb) + cb + 16);
    cp16(sb + G_BLO + so,       (const char*)(Blo + gb) + cb);
    cp16(sb + G_BLO + so + 16,  (const char*)(Blo + gb) + cb + 16);
}

__device__ __forceinline__ void gemm_core(
    char* smem, const __nv_bfloat16* Ahi, const __nv_bfloat16* Alo,
    const __nv_bfloat16* Bhi, const __nv_bfloat16* Blo,
    int m0, int n0, float c[4][4][4])
{
    const int tid = threadIdx.x;
    const int lane = tid & 31;
    const int wid = tid >> 5;
    const int wm = wid >> 2, wn = wid & 3;
    const uint32_t sb = smem_u32(smem);

    const uint32_t a_lrow = lane % 16, a_koff = (lane >> 4) * 16;
    const uint32_t b_lrow = (lane % 8) + ((lane >> 4) << 3), b_koff = ((lane >> 3) & 1) * 16;

#pragma unroll
    for (int i = 0; i < 4; i++)
#pragma unroll
        for (int j = 0; j < 4; j++)
#pragma unroll
            for (int e = 0; e < 4; e++) c[i][j][e] = 0.0f;

    gemm_load_stage(sb, Ahi, Alo, Bhi, Blo, m0, n0, 0, tid);
    cp_commit();

    for (int it = 0; it < 24; it++) {
        if (it + 1 < 24) {
            gemm_load_stage(sb + ((it + 1) & 1) * GSTAGE, Ahi, Alo, Bhi, Blo,
                            m0, n0, (it + 1) * 32, tid);
            cp_commit();
            cp_wait<1>();
        } else {
            cp_wait<0>();
        }
        __syncthreads();
        const uint32_t st = sb + (it & 1) * GSTAGE;
#pragma unroll
        for (int ks = 0; ks < 2; ks++) {
            uint32_t ah[4][4], al[4][4], bh[4][2], bl[4][2];
#pragma unroll
            for (int nfp = 0; nfp < 2; nfp++) {
                uint32_t addr = st + G_BHI + (uint32_t)(wn * 32 + nfp * 16 + b_lrow) * 80 + ks * 32 + b_koff;
                ldsm4(addr, bh[2 * nfp][0], bh[2 * nfp][1], bh[2 * nfp + 1][0], bh[2 * nfp + 1][1]);
                ldsm4(addr + (G_BLO - G_BHI), bl[2 * nfp][0], bl[2 * nfp][1], bl[2 * nfp + 1][0], bl[2 * nfp + 1][1]);
            }
#pragma unroll
            for (int mf = 0; mf < 4; mf++) {
                uint32_t addr = st + (uint32_t)(wm * 64 + mf * 16 + a_lrow) * 80 + ks * 32 + a_koff;
                ldsm4(addr, ah[mf][0], ah[mf][1], ah[mf][2], ah[mf][3]);
                ldsm4(addr + G_ALO, al[mf][0], al[mf][1], al[mf][2], al[mf][3]);
            }
#pragma unroll
            for (int mf = 0; mf < 4; mf++)
#pragma unroll
                for (int nf = 0; nf < 4; nf++) {
                    mma16816(c[mf][nf], ah[mf], bh[nf]);
                    mma16816(c[mf][nf], ah[mf], bl[nf]);
                    mma16816(c[mf][nf], al[mf], bh[nf]);
                }
        }
        __syncthreads();
    }
}

// ---------------------------------------------------------------------------
// QKV GEMM kernel: grid (2304/128=18, 4096/128=32), 256 threads
// ---------------------------------------------------------------------------
__device__ __forceinline__ void qkv_store(int s, int rowg, int colg, float v0, float v1)
{
    const int b = rowg >> 11, n = rowg & 2047;
    const int rem = colg - s * CDIM;
    const int h = rem >> 6, d = rem & 63;
    if (s == 0) { v0 *= SCALEF; v1 *= SCALEF; }
    __nv_bfloat16 h0 = __float2bfloat16_rn(v0), h1 = __float2bfloat16_rn(v1);
    __nv_bfloat16 l0 = __float2bfloat16_rn(v0 - __bfloat162float(h0));
    __nv_bfloat16 l1 = __float2bfloat16_rn(v1 - __bfloat162float(h1));
    if (s == 2) {
        const size_t base = ((size_t)(b * HEADS + h) * HDIM) * SEQ;
        g_vt_hi[base + (size_t)d * SEQ + n]       = h0;
        g_vt_hi[base + (size_t)(d + 1) * SEQ + n] = h1;
        g_vt_lo[base + (size_t)d * SEQ + n]       = l0;
        g_vt_lo[base + (size_t)(d + 1) * SEQ + n] = l1;
    } else {
        const size_t off = ((size_t)(b * HEADS + h) * SEQ + n) * HDIM + d;
        __nv_bfloat16* dh = (s == 0) ? g_q_hi : g_k_hi;
        __nv_bfloat16* dl = (s == 0) ? g_q_lo : g_k_lo;
        __nv_bfloat162 H; H.x = h0; H.y = h1;
        __nv_bfloat162 L; L.x = l0; L.y = l1;
        *reinterpret_cast<__nv_bfloat162*>(dh + off) = H;
        *reinterpret_cast<__nv_bfloat162*>(dl + off) = L;
    }
}

__global__ __launch_bounds__(256, 1) void qkv_mma()
{
    extern __shared__ char smem[];
    const int n0 = blockIdx.x * 128;
    const int m0 = blockIdx.y * 128;
    const int lane = threadIdx.x & 31;
    const int wid = threadIdx.x >> 5;
    const int wm = wid >> 2, wn = wid & 3;

    float c[4][4][4];
    gemm_core(smem, g_x_hi, g_x_lo, g_wqkv_hi, g_wqkv_lo, m0, n0, c);

    const int s = n0 / CDIM;
#pragma unroll
    for (int mf = 0; mf < 4; mf++)
#pragma unroll
        for (int nf = 0; nf < 4; nf++) {
            const int rg = m0 + wm * 64 + mf * 16 + (lane >> 2);
            const int cg = n0 + wn * 32 + nf * 8 + (lane & 3) * 2;
            qkv_store(s, rg,     cg, c[mf][nf][0], c[mf][nf][1]);
            qkv_store(s, rg + 8, cg, c[mf][nf][2], c[mf][nf][3]);
        }
}

// ---------------------------------------------------------------------------
// Output projection kernel: grid (768/128=6, 4096/128=32)
// ---------------------------------------------------------------------------
__global__ __launch_bounds__(256, 1) void proj_mma(const float* __restrict__ bias,
                                                   float* __restrict__ out)
{
    extern __shared__ char smem[];
    const int n0 = blockIdx.x * 128;
    const int m0 = blockIdx.y * 128;
    const int lane = threadIdx.x & 31;
    const int wid = threadIdx.x >> 5;
    const int wm = wid >> 2, wn = wid & 3;

    float c[4][4][4];
    gemm_core(smem, g_ctx_hi, g_ctx_lo, g_wproj_hi, g_wproj_lo, m0, n0, c);

#pragma unroll
    for (int mf = 0; mf < 4; mf++)
#pragma unroll
        for (int nf = 0; nf < 4; nf++) {
            const int rg = m0 + wm * 64 + mf * 16 + (lane >> 2);
            const int cg = n0 + wn * 32 + nf * 8 + (lane & 3) * 2;
            const float b0 = bias[cg], b1 = bias[cg + 1];
            float2 v0 = make_float2(c[mf][nf][0] + b0, c[mf][nf][1] + b1);
            float2 v1 = make_float2(c[mf][nf][2] + b0, c[mf][nf][3] + b1);
            *reinterpret_cast<float2*>(out + (size_t)rg * CDIM + cg) = v0;
            *reinterpret_cast<float2*>(out + (size_t)(rg + 8) * CDIM + cg) = v1;
        }
}

// ---------------------------------------------------------------------------
// Flash attention (warp-MMA, FA2-style). grid (SEQ/128=16, BH=24), 256 threads.
// Warp w owns q-rows [16w, 16w+16). S and P live in registers only.
// smem: Qhi 18432 | Qlo 18432 | 2 stages x [Khi 9216|Klo 9216|Vthi 9216|Vtlo 9216]
// ---------------------------------------------------------------------------
#define AQ_LO    18432
#define AKV      36864
#define ASTAGE   36864
#define AK_LO    9216
#define AV_HI    18432
#define AV_LO    27648
#define ATTN_SMEM (AKV + 2 * ASTAGE)   // 110592

__device__ __forceinline__ void attn_load_stage(
    uint32_t sb, const __nv_bfloat16* Kh, const __nv_bfloat16* Kl,
    const __nv_bfloat16* Vh, const __nv_bfloat16* Vl, int kv0, int tid)
{
    const int row = tid >> 2;                 // 0..63
    const int cb  = (tid & 3) * 32;           // byte offset in 128B row
    const uint32_t so = (uint32_t)row * 144 + cb;
    const char* kh = (const char*)(Kh + (size_t)(kv0 + row) * HDIM) + cb;
    const char* kl = (const char*)(Kl + (size_t)(kv0 + row) * HDIM) + cb;
    const char* vh = (const char*)(Vh + (size_t)row * SEQ + kv0) + cb;
    const char* vl = (const char*)(Vl + (size_t)row * SEQ + kv0) + cb;
    cp16(sb + so, kh);            cp16(sb + so + 16, kh + 16);
    cp16(sb + AK_LO + so, kl);    cp16(sb + AK_LO + so + 16, kl + 16);
    cp16(sb + AV_HI + so, vh);    cp16(sb + AV_HI + so + 16, vh + 16);
    cp16(sb + AV_LO + so, vl);    cp16(sb + AV_LO + so + 16, vl + 16);
}

__global__ __launch_bounds__(256, 1) void attn_mma()
{
    extern __shared__ char smem[];
    const uint32_t sb = smem_u32(smem);
    const int q0 = blockIdx.x * 128;
    const int bh = blockIdx.y;
    const int tid = threadIdx.x;
    const int lane = tid & 31;
    const int wid = tid >> 5;

    const __nv_bfloat16* Qh = g_q_hi + (size_t)bh * SEQ * HDIM;
    const __nv_bfloat16* Ql = g_q_lo + (size_t)bh * SEQ * HDIM;
    const __nv_bfloat16* Kh = g_k_hi + (size_t)bh * SEQ * HDIM;
    const __nv_bfloat16* Kl = g_k_lo + (size_t)bh * SEQ * HDIM;
    const __nv_bfloat16* Vh = g_vt_hi + (size_t)bh * HDIM * SEQ;
    const __nv_bfloat16* Vl = g_vt_lo + (size_t)bh * HDIM * SEQ;

    // Load Q tile into smem (rows padded to 144B)
    {
        const int row = tid >> 1;
        const int cb = (tid & 1) * 64;
        const uint4* qs = reinterpret_cast<const uint4*>((const char*)(Qh + (size_t)(q0 + row) * HDIM) + cb);
        const uint4* ql = reinterpret_cast<const uint4*>((const char*)(Ql + (size_t)(q0 + row) * HDIM) + cb);
        uint4* dh = reinterpret_cast<uint4*>(smem + (uint32_t)row * 144 + cb);
        uint4* dl = reinterpret_cast<uint4*>(smem + AQ_LO + (uint32_t)row * 144 + cb);
#pragma unroll
        for (int i = 0; i < 4; i++) { dh[i] = qs[i]; dl[i] = ql[i]; }
    }
    // Prefetch first KV stage
    attn_load_stage(sb + AKV, Kh, Kl, Vh, Vl, 0, tid);
    cp_commit();
    __syncthreads();

    const uint32_t a_lrow = lane % 16, a_koff = (lane >> 4) * 16;
    const uint32_t b_lrow = (lane % 8) + ((lane >> 4) << 3), b_koff = ((lane >> 3) & 1) * 16;

    // Hoist Q fragments (constant across kv tiles)
    uint32_t qh[4][4], qlr[4][4];
#pragma unroll
    for (int ks = 0; ks < 4; ks++) {
        uint32_t addr = sb + (uint32_t)(wid * 16 + a_lrow) * 144 + ks * 32 + a_koff;
        ldsm4(addr, qh[ks][0], qh[ks][1], qh[ks][2], qh[ks][3]);
        ldsm4(addr + AQ_LO, qlr[ks][0], qlr[ks][1], qlr[ks][2], qlr[ks][3]);
    }

    float o[8][4];
#pragma unroll
    for (int nf = 0; nf < 8; nf++)
#pragma unroll
        for (int e = 0; e < 4; e++) o[nf][e] = 0.0f;
    float m_run0 = -1e30f, m_run1 = -1e30f, l_run0 = 0.0f, l_run1 = 0.0f;

    for (int it = 0; it < SEQ / 64; it++) {
        if (it + 1 < SEQ / 64) {
            attn_load_stage(sb + AKV + ((it + 1) & 1) * ASTAGE, Kh, Kl, Vh, Vl, (it + 1) * 64, tid);
            cp_commit();
            cp_wait<1>();
        } else {
            cp_wait<0>();
        }
        __syncthreads();
        const uint32_t st = sb + AKV + (it & 1) * ASTAGE;

        // ---- S = Q K^T (3-pass split) ----
        float s[8][4];
#pragma unroll
        for (int nf = 0; nf < 8; nf++)
#pragma unroll
            for (int e = 0; e < 4; e++) s[nf][e] = 0.0f;
#pragma unroll
        for (int ks = 0; ks < 4; ks++) {
            uint32_t kbh[8][2], kbl[8][2];
#pragma unroll
            for (int nfp = 0; nfp < 4; nfp++) {
                uint32_t addr = st + (uint32_t)(nfp * 16 + b_lrow) * 144 + ks * 32 + b_koff;
                ldsm4(addr, kbh[2 * nfp][0], kbh[2 * nfp][1], kbh[2 * nfp + 1][0], kbh[2 * nfp + 1][1]);
                ldsm4(addr + AK_LO, kbl[2 * nfp][0], kbl[2 * nfp][1], kbl[2 * nfp + 1][0], kbl[2 * nfp + 1][1]);
            }
#pragma unroll
            for (int nf = 0; nf < 8; nf++) {
                mma16816(s[nf], qh[ks], kbh[nf]);
                mma16816(s[nf], qh[ks], kbl[nf]);
                mma16816(s[nf], qlr[ks], kbh[nf]);
            }
        }

        // ---- online softmax (rows l/4 and l/4+8; reduce over 4-lane group) ----
        float vm0 = -1e30f, vm1 = -1e30f;
#pragma unroll
        for (int nf = 0; nf < 8; nf++) {
            vm0 = fmaxf(vm0, fmaxf(s[nf][0], s[nf][1]));
            vm1 = fmaxf(vm1, fmaxf(s[nf][2], s[nf][3]));
        }
        vm0 = fmaxf(vm0, __shfl_xor_sync(0xffffffff, vm0, 1));
        vm0 = fmaxf(vm0, __shfl_xor_sync(0xffffffff, vm0, 2));
        vm1 = fmaxf(vm1, __shfl_xor_sync(0xffffffff, vm1, 1));
        vm1 = fmaxf(vm1, __shfl_xor_sync(0xffffffff, vm1, 2));
        const float nm0 = fmaxf(m_run0, vm0);
        const float nm1 = fmaxf(m_run1, vm1);
        const float corr0 = __expf(m_run0 - nm0);
        const float corr1 = __expf(m_run1 - nm1);
        float sum0 = 0.0f, sum1 = 0.0f;
#pragma unroll
        for (int nf = 0; nf < 8; nf++) {
            s[nf][0] = __expf(s[nf][0] - nm0); sum0 += s[nf][0];
            s[nf][1] = __expf(s[nf][1] - nm0); sum0 += s[nf][1];
            s[nf][2] = __expf(s[nf][2] - nm1); sum1 += s[nf][2];
            s[nf][3] = __expf(s[nf][3] - nm1); sum1 += s[nf][3];
        }
        sum0 += __shfl_xor_sync(0xffffffff, sum0, 1);
        sum0 += __shfl_xor_sync(0xffffffff, sum0, 2);
        sum1 += __shfl_xor_sync(0xffffffff, sum1, 1);
        sum1 += __shfl_xor_sync(0xffffffff, sum1, 2);
        l_run0 = l_run0 * corr0 + sum0;
        l_run1 = l_run1 * corr1 + sum1;
        m_run0 = nm0; m_run1 = nm1;
#pragma unroll
        for (int nf = 0; nf < 8; nf++) {
            o[nf][0] *= corr0; o[nf][1] *= corr0;
            o[nf][2] *= corr1; o[nf][3] *= corr1;
        }

        // ---- O += P V (P repacked in registers as A-frags, split hi/lo) ----
#pragma unroll
        for (int ks2 = 0; ks2 < 4; ks2++) {
            uint32_t pah[4], pal[4];
            split2(s[2 * ks2][0],     s[2 * ks2][1],     pah[0], pal[0]);
            split2(s[2 * ks2][2],     s[2 * ks2][3],     pah[1], pal[1]);
            split2(s[2 * ks2 + 1][0], s[2 * ks2 + 1][1], pah[2], pal[2]);
            split2(s[2 * ks2 + 1][2], s[2 * ks2 + 1][3], pah[3], pal[3]);
            uint32_t vbh[8][2], vbl[8][2];
#pragma unroll
            for (int nfp = 0; nfp < 4; nfp++) {
                uint32_t addr = st + AV_HI + (uint32_t)(nfp * 16 + b_lrow) * 144 + ks2 * 32 + b_koff;
                ldsm4(addr, vbh[2 * nfp][0], vbh[2 * nfp][1], vbh[2 * nfp + 1][0], vbh[2 * nfp + 1][1]);
                ldsm4(addr + (AV_LO - AV_HI), vbl[2 * nfp][0], vbl[2 * nfp][1], vbl[2 * nfp + 1][0], vbl[2 * nfp + 1][1]);
            }
#pragma unroll
            for (int nf = 0; nf < 8; nf++) {
                mma16816(o[nf], pah, vbh[nf]);
                mma16816(o[nf], pah, vbl[nf]);
                mma16816(o[nf], pal, vbh[nf]);
            }
        }
        __syncthreads();
    }

    // ---- epilogue: normalize, split, write ctx ----
    const int b = bh / HEADS;
    const int h = bh % HEADS;
    const float inv0 = 1.0f / l_run0;
    const float inv1 = 1.0f / l_run1;
    const int r0 = q0 + wid * 16 + (lane >> 2);
#pragma unroll
    for (int nf = 0; nf < 8; nf++) {
        const int d = nf * 8 + (lane & 3) * 2;
        uint32_t H, L;
        split2(o[nf][0] * inv0, o[nf][1] * inv0, H, L);
        size_t off = ((size_t)(b * SEQ + r0)) * CDIM + h * HDIM + d;
        *reinterpret_cast<uint32_t*>(g_ctx_hi + off) = H;
        *reinterpret_cast<uint32_t*>(g_ctx_lo + off) = L;
        split2(o[nf][2] * inv1, o[nf][3] * inv1, H, L);
        off = ((size_t)(b * SEQ + r0 + 8)) * CDIM + h * HDIM + d;
        *reinterpret_cast<uint32_t*>(g_ctx_hi + off) = H;
        *reinterpret_cast<uint32_t*>(g_ctx_lo + off) = L;
    }
}

// ---------------------------------------------------------------------------
// Launch
// ---------------------------------------------------------------------------
extern "C" void kernel_launch(void* const* d_in, const int* in_sizes, int n_in,
                              void* d_out, int out_size)
{
    const float* x      = (const float*)d_in[0];
    const float* w_qkv  = (const float*)d_in[1];
    const float* w_proj = (const float*)d_in[2];
    const float* b_proj = (const float*)d_in[3];
    float* out = (float*)d_out;
    (void)in_sizes; (void)n_in; (void)out_size;

    cudaFuncSetAttribute(qkv_mma,  cudaFuncAttributeMaxDynamicSharedMemorySize, GEMM_SMEM);
    cudaFuncSetAttribute(attn_mma, cudaFuncAttributeMaxDynamicSharedMemorySize, ATTN_SMEM);
    cudaFuncSetAttribute(proj_mma, cudaFuncAttributeMaxDynamicSharedMemorySize, GEMM_SMEM);

    __nv_bfloat16 *xh, *xl, *wh, *wl, *ph, *pl;
    cudaGetSymbolAddress((void**)&xh, g_x_hi);
    cudaGetSymbolAddress((void**)&xl, g_x_lo);
    cudaGetSymbolAddress((void**)&wh, g_wqkv_hi);
    cudaGetSymbolAddress((void**)&wl, g_wqkv_lo);
    cudaGetSymbolAddress((void**)&ph, g_wproj_hi);
    cudaGetSymbolAddress((void**)&pl, g_wproj_lo);

    convert_split<<<1024, 256>>>(x, xh, xl, MROWS * CDIM);
    convert_split<<<1024, 256>>>(w_qkv, wh, wl, QKV_N * CDIM);
    convert_split<<<512, 256>>>(w_proj, ph, pl, CDIM * CDIM);

    qkv_mma<<<dim3(QKV_N / 128, MROWS / 128), 256, GEMM_SMEM>>>();
    attn_mma<<<dim3(SEQ / 128, BH), 256, ATTN_SMEM>>>();
    proj_mma<<<dim3(CDIM / 128, MROWS / 128), 256, GEMM_SMEM>>>(b_proj, out);
}

// round 6
// speedup vs baseline: 2.8054x; 1.0708x over previous
#include <cuda_runtime.h>
#include <cuda_bf16.h>
#include <cstdint>

#define BATCH   2
#define SEQ     2048
#define CDIM    768
#define HEADS   12
#define HDIM    64
#define QKV_N   2304
#define MROWS   4096
#define BH      24
#define SCALEF  0.125f

// ---------------------------------------------------------------------------
// Scratch
// ---------------------------------------------------------------------------
__device__ __nv_bfloat16 g_x_hi[MROWS * CDIM];
__device__ __nv_bfloat16 g_x_lo[MROWS * CDIM];
__device__ __nv_bfloat16 g_wqkv_hi[QKV_N * CDIM];
__device__ __nv_bfloat16 g_wqkv_lo[QKV_N * CDIM];
__device__ __nv_bfloat16 g_wproj_hi[CDIM * CDIM];
__device__ __nv_bfloat16 g_wproj_lo[CDIM * CDIM];
__device__ __nv_bfloat16 g_q_hi[BH * SEQ * HDIM];    // [b,h,n,d], pre-scaled by 1/8
__device__ __nv_bfloat16 g_q_lo[BH * SEQ * HDIM];
__device__ __nv_bfloat16 g_k_hi[BH * SEQ * HDIM];
__device__ __nv_bfloat16 g_k_lo[BH * SEQ * HDIM];
__device__ __nv_bfloat16 g_vt_hi[BH * HDIM * SEQ];   // [b,h,d,n]
__device__ __nv_bfloat16 g_vt_lo[BH * HDIM * SEQ];
__device__ __nv_bfloat16 g_ctx_hi[MROWS * CDIM];
__device__ __nv_bfloat16 g_ctx_lo[MROWS * CDIM];

// ---------------------------------------------------------------------------
// Helpers (plain sm_80-era PTX: valid on compute_100 without 'a')
// ---------------------------------------------------------------------------
__device__ __forceinline__ uint32_t smem_u32(const void* p) {
    uint32_t a;
    asm("{ .reg .u64 t; cvta.to.shared.u64 t, %1; cvt.u32.u64 %0, t; }" : "=r"(a) : "l"(p));
    return a;
}
__device__ __forceinline__ void cp16(uint32_t dst, const void* src) {
    asm volatile("cp.async.cg.shared.global [%0], [%1], 16;" :: "r"(dst), "l"(src));
}
__device__ __forceinline__ void cp_commit() { asm volatile("cp.async.commit_group;"); }
template <int N> __device__ __forceinline__ void cp_wait() {
    asm volatile("cp.async.wait_group %0;" :: "n"(N));
}
__device__ __forceinline__ void ldsm4(uint32_t a, uint32_t& r0, uint32_t& r1, uint32_t& r2, uint32_t& r3) {
    asm volatile("ldmatrix.sync.aligned.m8n8.x4.shared.b16 {%0,%1,%2,%3}, [%4];"
                 : "=r"(r0), "=r"(r1), "=r"(r2), "=r"(r3) : "r"(a));
}
__device__ __forceinline__ void mma16816(float* c, const uint32_t* a, const uint32_t* b) {
    asm volatile("mma.sync.aligned.m16n8k16.row.col.f32.bf16.bf16.f32 "
                 "{%0,%1,%2,%3}, {%4,%5,%6,%7}, {%8,%9}, {%0,%1,%2,%3};"
                 : "+f"(c[0]), "+f"(c[1]), "+f"(c[2]), "+f"(c[3])
                 : "r"(a[0]), "r"(a[1]), "r"(a[2]), "r"(a[3]), "r"(b[0]), "r"(b[1]));
}
__device__ __forceinline__ void split2(float x, float y, uint32_t& hi, uint32_t& lo) {
    __nv_bfloat16 hx = __float2bfloat16_rn(x), hy = __float2bfloat16_rn(y);
    __nv_bfloat162 H; H.x = hx; H.y = hy;
    __nv_bfloat162 L;
    L.x = __float2bfloat16_rn(x - __bfloat162float(hx));
    L.y = __float2bfloat16_rn(y - __bfloat162float(hy));
    hi = *reinterpret_cast<uint32_t*>(&H);
    lo = *reinterpret_cast<uint32_t*>(&L);
}

// ---------------------------------------------------------------------------
// Convert fp32 -> split bf16
// ---------------------------------------------------------------------------
__global__ void convert_split(const float* __restrict__ src,
                              __nv_bfloat16* __restrict__ hi,
                              __nv_bfloat16* __restrict__ lo, int n)
{
    int i = blockIdx.x * blockDim.x + threadIdx.x;
    for (; i < n; i += gridDim.x * blockDim.x) {
        float v = src[i];
        __nv_bfloat16 h = __float2bfloat16_rn(v);
        hi[i] = h;
        lo[i] = __float2bfloat16_rn(v - __bfloat162float(h));
    }
}

// ---------------------------------------------------------------------------
// GEMM core: C(128x128) = (Ahi+Alo)(Bhi+Blo)^T over K=768. 256 threads.
// smem stage: [Ahi 10240][Alo 10240][Bhi 10240][Blo 10240], rows padded to 80B.
// ---------------------------------------------------------------------------
#define GSTAGE   40960
#define G_ALO    10240
#define G_BHI    20480
#define G_BLO    30720
#define GEMM_SMEM (2 * GSTAGE)

__device__ __forceinline__ void gemm_load_stage(
    uint32_t sb, const __nv_bfloat16* Ahi, const __nv_bfloat16* Alo,
    const __nv_bfloat16* Bhi, const __nv_bfloat16* Blo,
    int m0, int n0, int k0, int tid)
{
    const int row = tid >> 1;
    const int cb  = (tid & 1) * 32;                 // byte offset in 64B row
    const size_t ga = (size_t)(m0 + row) * CDIM + k0;
    const size_t gb = (size_t)(n0 + row) * CDIM + k0;
    const uint32_t so = (uint32_t)row * 80 + cb;
    cp16(sb + so,               (const char*)(Ahi + ga) + cb);
    cp16(sb + so + 16,          (const char*)(Ahi + ga) + cb + 16);
    cp16(sb + G_ALO + so,       (const char*)(Alo + ga) + cb);
    cp16(sb + G_ALO + so + 16,  (const char*)(Alo + ga) + cb + 16);
    cp16(sb + G_BHI + so,       (const char*)(Bhi + gb) + cb);
    cp16(sb + G_BHI + so + 16,  (const char*)(Bhi + gb) + cb + 16);
    cp16(sb + G_BLO + so,       (const char*)(Blo + gb) + cb);
    cp16(sb + G_BLO + so + 16,  (const char*)(Blo + gb) + cb + 16);
}

__device__ __forceinline__ void gemm_core(
    char* smem, const __nv_bfloat16* Ahi, const __nv_bfloat16* Alo,
    const __nv_bfloat16* Bhi, const __nv_bfloat16* Blo,
    int m0, int n0, float c[4][4][4])
{
    const int tid = threadIdx.x;
    const int lane = tid & 31;
    const int wid = tid >> 5;
    const int wm = wid >> 2, wn = wid & 3;
    const uint32_t sb = smem_u32(smem);

    const uint32_t a_lrow = lane % 16, a_koff = (lane >> 4) * 16;
    const uint32_t b_lrow = (lane % 8) + ((lane >> 4) << 3), b_koff = ((lane >> 3) & 1) * 16;

#pragma unroll
    for (int i = 0; i < 4; i++)
#pragma unroll
        for (int j = 0; j < 4; j++)
#pragma unroll
            for (int e = 0; e < 4; e++) c[i][j][e] = 0.0f;

    gemm_load_stage(sb, Ahi, Alo, Bhi, Blo, m0, n0, 0, tid);
    cp_commit();

    for (int it = 0; it < 24; it++) {
        if (it + 1 < 24) {
            gemm_load_stage(sb + ((it + 1) & 1) * GSTAGE, Ahi, Alo, Bhi, Blo,
                            m0, n0, (it + 1) * 32, tid);
            cp_commit();
            cp_wait<1>();
        } else {
            cp_wait<0>();
        }
        __syncthreads();
        const uint32_t st = sb + (it & 1) * GSTAGE;
#pragma unroll
        for (int ks = 0; ks < 2; ks++) {
            uint32_t ah[4][4], al[4][4], bh[4][2], bl[4][2];
#pragma unroll
            for (int nfp = 0; nfp < 2; nfp++) {
                uint32_t addr = st + G_BHI + (uint32_t)(wn * 32 + nfp * 16 + b_lrow) * 80 + ks * 32 + b_koff;
                ldsm4(addr, bh[2 * nfp][0], bh[2 * nfp][1], bh[2 * nfp + 1][0], bh[2 * nfp + 1][1]);
                ldsm4(addr + (G_BLO - G_BHI), bl[2 * nfp][0], bl[2 * nfp][1], bl[2 * nfp + 1][0], bl[2 * nfp + 1][1]);
            }
#pragma unroll
            for (int mf = 0; mf < 4; mf++) {
                uint32_t addr = st + (uint32_t)(wm * 64 + mf * 16 + a_lrow) * 80 + ks * 32 + a_koff;
                ldsm4(addr, ah[mf][0], ah[mf][1], ah[mf][2], ah[mf][3]);
                ldsm4(addr + G_ALO, al[mf][0], al[mf][1], al[mf][2], al[mf][3]);
            }
#pragma unroll
            for (int mf = 0; mf < 4; mf++)
#pragma unroll
                for (int nf = 0; nf < 4; nf++) {
                    mma16816(c[mf][nf], ah[mf], bh[nf]);
                    mma16816(c[mf][nf], ah[mf], bl[nf]);
                    mma16816(c[mf][nf], al[mf], bh[nf]);
                }
        }
        __syncthreads();
    }
}

// ---------------------------------------------------------------------------
// QKV GEMM kernel: grid (2304/128=18, 4096/128=32), 256 threads, 2 CTAs/SM
// ---------------------------------------------------------------------------
__device__ __forceinline__ void qkv_store(int s, int rowg, int colg, float v0, float v1)
{
    const int b = rowg >> 11, n = rowg & 2047;
    const int rem = colg - s * CDIM;
    const int h = rem >> 6, d = rem & 63;
    if (s == 0) { v0 *= SCALEF; v1 *= SCALEF; }
    __nv_bfloat16 h0 = __float2bfloat16_rn(v0), h1 = __float2bfloat16_rn(v1);
    __nv_bfloat16 l0 = __float2bfloat16_rn(v0 - __bfloat162float(h0));
    __nv_bfloat16 l1 = __float2bfloat16_rn(v1 - __bfloat162float(h1));
    if (s == 2) {
        const size_t base = ((size_t)(b * HEADS + h) * HDIM) * SEQ;
        g_vt_hi[base + (size_t)d * SEQ + n]       = h0;
        g_vt_hi[base + (size_t)(d + 1) * SEQ + n] = h1;
        g_vt_lo[base + (size_t)d * SEQ + n]       = l0;
        g_vt_lo[base + (size_t)(d + 1) * SEQ + n] = l1;
    } else {
        const size_t off = ((size_t)(b * HEADS + h) * SEQ + n) * HDIM + d;
        __nv_bfloat16* dh = (s == 0) ? g_q_hi : g_k_hi;
        __nv_bfloat16* dl = (s == 0) ? g_q_lo : g_k_lo;
        __nv_bfloat162 H; H.x = h0; H.y = h1;
        __nv_bfloat162 L; L.x = l0; L.y = l1;
        *reinterpret_cast<__nv_bfloat162*>(dh + off) = H;
        *reinterpret_cast<__nv_bfloat162*>(dl + off) = L;
    }
}

__global__ __launch_bounds__(256, 2) void qkv_mma()
{
    extern __shared__ char smem[];
    const int n0 = blockIdx.x * 128;
    const int m0 = blockIdx.y * 128;
    const int lane = threadIdx.x & 31;
    const int wid = threadIdx.x >> 5;
    const int wm = wid >> 2, wn = wid & 3;

    float c[4][4][4];
    gemm_core(smem, g_x_hi, g_x_lo, g_wqkv_hi, g_wqkv_lo, m0, n0, c);

    const int s = n0 / CDIM;
#pragma unroll
    for (int mf = 0; mf < 4; mf++)
#pragma unroll
        for (int nf = 0; nf < 4; nf++) {
            const int rg = m0 + wm * 64 + mf * 16 + (lane >> 2);
            const int cg = n0 + wn * 32 + nf * 8 + (lane & 3) * 2;
            qkv_store(s, rg,     cg, c[mf][nf][0], c[mf][nf][1]);
            qkv_store(s, rg + 8, cg, c[mf][nf][2], c[mf][nf][3]);
        }
}

// ---------------------------------------------------------------------------
// Output projection kernel: grid (768/128=6, 4096/128=32), 2 CTAs/SM
// ---------------------------------------------------------------------------
__global__ __launch_bounds__(256, 2) void proj_mma(const float* __restrict__ bias,
                                                   float* __restrict__ out)
{
    extern __shared__ char smem[];
    const int n0 = blockIdx.x * 128;
    const int m0 = blockIdx.y * 128;
    const int lane = threadIdx.x & 31;
    const int wid = threadIdx.x >> 5;
    const int wm = wid >> 2, wn = wid & 3;

    float c[4][4][4];
    gemm_core(smem, g_ctx_hi, g_ctx_lo, g_wproj_hi, g_wproj_lo, m0, n0, c);

#pragma unroll
    for (int mf = 0; mf < 4; mf++)
#pragma unroll
        for (int nf = 0; nf < 4; nf++) {
            const int rg = m0 + wm * 64 + mf * 16 + (lane >> 2);
            const int cg = n0 + wn * 32 + nf * 8 + (lane & 3) * 2;
            const float b0 = bias[cg], b1 = bias[cg + 1];
            float2 v0 = make_float2(c[mf][nf][0] + b0, c[mf][nf][1] + b1);
            float2 v1 = make_float2(c[mf][nf][2] + b0, c[mf][nf][3] + b1);
            *reinterpret_cast<float2*>(out + (size_t)rg * CDIM + cg) = v0;
            *reinterpret_cast<float2*>(out + (size_t)(rg + 8) * CDIM + cg) = v1;
        }
}

// ---------------------------------------------------------------------------
// Flash attention (warp-MMA, FA2-style). grid (SEQ/128=16, BH=24), 256 threads.
// Warp w owns q-rows [16w, 16w+16). S and P live in registers only. 2 CTAs/SM.
// smem: Qhi 18432 | Qlo 18432 | 2 stages x [Khi 9216|Klo 9216|Vthi 9216|Vtlo 9216]
// ---------------------------------------------------------------------------
#define AQ_LO    18432
#define AKV      36864
#define ASTAGE   36864
#define AK_LO    9216
#define AV_HI    18432
#define AV_LO    27648
#define ATTN_SMEM (AKV + 2 * ASTAGE)   // 110592

__device__ __forceinline__ void attn_load_stage(
    uint32_t sb, const __nv_bfloat16* Kh, const __nv_bfloat16* Kl,
    const __nv_bfloat16* Vh, const __nv_bfloat16* Vl, int kv0, int tid)
{
    const int row = tid >> 2;                 // 0..63
    const int cb  = (tid & 3) * 32;           // byte offset in 128B row
    const uint32_t so = (uint32_t)row * 144 + cb;
    const char* kh = (const char*)(Kh + (size_t)(kv0 + row) * HDIM) + cb;
    const char* kl = (const char*)(Kl + (size_t)(kv0 + row) * HDIM) + cb;
    const char* vh = (const char*)(Vh + (size_t)row * SEQ + kv0) + cb;
    const char* vl = (const char*)(Vl + (size_t)row * SEQ + kv0) + cb;
    cp16(sb + so, kh);            cp16(sb + so + 16, kh + 16);
    cp16(sb + AK_LO + so, kl);    cp16(sb + AK_LO + so + 16, kl + 16);
    cp16(sb + AV_HI + so, vh);    cp16(sb + AV_HI + so + 16, vh + 16);
    cp16(sb + AV_LO + so, vl);    cp16(sb + AV_LO + so + 16, vl + 16);
}

__global__ __launch_bounds__(256, 2) void attn_mma()
{
    extern __shared__ char smem[];
    const uint32_t sb = smem_u32(smem);
    const int q0 = blockIdx.x * 128;
    const int bh = blockIdx.y;
    const int tid = threadIdx.x;
    const int lane = tid & 31;
    const int wid = tid >> 5;

    const __nv_bfloat16* Qh = g_q_hi + (size_t)bh * SEQ * HDIM;
    const __nv_bfloat16* Ql = g_q_lo + (size_t)bh * SEQ * HDIM;
    const __nv_bfloat16* Kh = g_k_hi + (size_t)bh * SEQ * HDIM;
    const __nv_bfloat16* Kl = g_k_lo + (size_t)bh * SEQ * HDIM;
    const __nv_bfloat16* Vh = g_vt_hi + (size_t)bh * HDIM * SEQ;
    const __nv_bfloat16* Vl = g_vt_lo + (size_t)bh * HDIM * SEQ;

    // Load Q tile into smem (rows padded to 144B)
    {
        const int row = tid >> 1;
        const int cb = (tid & 1) * 64;
        const uint4* qs = reinterpret_cast<const uint4*>((const char*)(Qh + (size_t)(q0 + row) * HDIM) + cb);
        const uint4* ql = reinterpret_cast<const uint4*>((const char*)(Ql + (size_t)(q0 + row) * HDIM) + cb);
        uint4* dh = reinterpret_cast<uint4*>(smem + (uint32_t)row * 144 + cb);
        uint4* dl = reinterpret_cast<uint4*>(smem + AQ_LO + (uint32_t)row * 144 + cb);
#pragma unroll
        for (int i = 0; i < 4; i++) { dh[i] = qs[i]; dl[i] = ql[i]; }
    }
    // Prefetch first KV stage
    attn_load_stage(sb + AKV, Kh, Kl, Vh, Vl, 0, tid);
    cp_commit();
    __syncthreads();

    const uint32_t a_lrow = lane % 16, a_koff = (lane >> 4) * 16;
    const uint32_t b_lrow = (lane % 8) + ((lane >> 4) << 3), b_koff = ((lane >> 3) & 1) * 16;

    // Hoist Q fragments (constant across kv tiles)
    uint32_t qh[4][4], qlr[4][4];
#pragma unroll
    for (int ks = 0; ks < 4; ks++) {
        uint32_t addr = sb + (uint32_t)(wid * 16 + a_lrow) * 144 + ks * 32 + a_koff;
        ldsm4(addr, qh[ks][0], qh[ks][1], qh[ks][2], qh[ks][3]);
        ldsm4(addr + AQ_LO, qlr[ks][0], qlr[ks][1], qlr[ks][2], qlr[ks][3]);
    }

    float o[8][4];
#pragma unroll
    for (int nf = 0; nf < 8; nf++)
#pragma unroll
        for (int e = 0; e < 4; e++) o[nf][e] = 0.0f;
    float m_run0 = -1e30f, m_run1 = -1e30f, l_run0 = 0.0f, l_run1 = 0.0f;

    for (int it = 0; it < SEQ / 64; it++) {
        if (it + 1 < SEQ / 64) {
            attn_load_stage(sb + AKV + ((it + 1) & 1) * ASTAGE, Kh, Kl, Vh, Vl, (it + 1) * 64, tid);
            cp_commit();
            cp_wait<1>();
        } else {
            cp_wait<0>();
        }
        __syncthreads();
        const uint32_t st = sb + AKV + (it & 1) * ASTAGE;

        // ---- S = Q K^T (3-pass split) ----
        float s[8][4];
#pragma unroll
        for (int nf = 0; nf < 8; nf++)
#pragma unroll
            for (int e = 0; e < 4; e++) s[nf][e] = 0.0f;
#pragma unroll
        for (int ks = 0; ks < 4; ks++) {
            uint32_t kbh[8][2], kbl[8][2];
#pragma unroll
            for (int nfp = 0; nfp < 4; nfp++) {
                uint32_t addr = st + (uint32_t)(nfp * 16 + b_lrow) * 144 + ks * 32 + b_koff;
                ldsm4(addr, kbh[2 * nfp][0], kbh[2 * nfp][1], kbh[2 * nfp + 1][0], kbh[2 * nfp + 1][1]);
                ldsm4(addr + AK_LO, kbl[2 * nfp][0], kbl[2 * nfp][1], kbl[2 * nfp + 1][0], kbl[2 * nfp + 1][1]);
            }
#pragma unroll
            for (int nf = 0; nf < 8; nf++) {
                mma16816(s[nf], qh[ks], kbh[nf]);
                mma16816(s[nf], qh[ks], kbl[nf]);
                mma16816(s[nf], qlr[ks], kbh[nf]);
            }
        }

        // ---- online softmax (rows l/4 and l/4+8; reduce over 4-lane group) ----
        float vm0 = -1e30f, vm1 = -1e30f;
#pragma unroll
        for (int nf = 0; nf < 8; nf++) {
            vm0 = fmaxf(vm0, fmaxf(s[nf][0], s[nf][1]));
            vm1 = fmaxf(vm1, fmaxf(s[nf][2], s[nf][3]));
        }
        vm0 = fmaxf(vm0, __shfl_xor_sync(0xffffffff, vm0, 1));
        vm0 = fmaxf(vm0, __shfl_xor_sync(0xffffffff, vm0, 2));
        vm1 = fmaxf(vm1, __shfl_xor_sync(0xffffffff, vm1, 1));
        vm1 = fmaxf(vm1, __shfl_xor_sync(0xffffffff, vm1, 2));
        const float nm0 = fmaxf(m_run0, vm0);
        const float nm1 = fmaxf(m_run1, vm1);
        const float corr0 = __expf(m_run0 - nm0);
        const float corr1 = __expf(m_run1 - nm1);
        float sum0 = 0.0f, sum1 = 0.0f;
#pragma unroll
        for (int nf = 0; nf < 8; nf++) {
            s[nf][0] = __expf(s[nf][0] - nm0); sum0 += s[nf][0];
            s[nf][1] = __expf(s[nf][1] - nm0); sum0 += s[nf][1];
            s[nf][2] = __expf(s[nf][2] - nm1); sum1 += s[nf][2];
            s[nf][3] = __expf(s[nf][3] - nm1); sum1 += s[nf][3];
        }
        sum0 += __shfl_xor_sync(0xffffffff, sum0, 1);
        sum0 += __shfl_xor_sync(0xffffffff, sum0, 2);
        sum1 += __shfl_xor_sync(0xffffffff, sum1, 1);
        sum1 += __shfl_xor_sync(0xffffffff, sum1, 2);
        l_run0 = l_run0 * corr0 + sum0;
        l_run1 = l_run1 * corr1 + sum1;
        m_run0 = nm0; m_run1 = nm1;
#pragma unroll
        for (int nf = 0; nf < 8; nf++) {
            o[nf][0] *= corr0; o[nf][1] *= corr0;
            o[nf][2] *= corr1; o[nf][3] *= corr1;
        }

        // ---- O += P V (P repacked in registers as A-frags, split hi/lo) ----
#pragma unroll
        for (int ks2 = 0; ks2 < 4; ks2++) {
            uint32_t pah[4], pal[4];
            split2(s[2 * ks2][0],     s[2 * ks2][1],     pah[0], pal[0]);
            split2(s[2 * ks2][2],     s[2 * ks2][3],     pah[1], pal[1]);
            split2(s[2 * ks2 + 1][0], s[2 * ks2 + 1][1], pah[2], pal[2]);
            split2(s[2 * ks2 + 1][2], s[2 * ks2 + 1][3], pah[3], pal[3]);
            uint32_t vbh[8][2], vbl[8][2];
#pragma unroll
            for (int nfp = 0; nfp < 4; nfp++) {
                uint32_t addr = st + AV_HI + (uint32_t)(nfp * 16 + b_lrow) * 144 + ks2 * 32 + b_koff;
                ldsm4(addr, vbh[2 * nfp][0], vbh[2 * nfp][1], vbh[2 * nfp + 1][0], vbh[2 * nfp + 1][1]);
                ldsm4(addr + (AV_LO - AV_HI), vbl[2 * nfp][0], vbl[2 * nfp][1], vbl[2 * nfp + 1][0], vbl[2 * nfp + 1][1]);
            }
#pragma unroll
            for (int nf = 0; nf < 8; nf++) {
                mma16816(o[nf], pah, vbh[nf]);
                mma16816(o[nf], pah, vbl[nf]);
                mma16816(o[nf], pal, vbh[nf]);
            }
        }
        __syncthreads();
    }

    // ---- epilogue: normalize, split, write ctx ----
    const int b = bh / HEADS;
    const int h = bh % HEADS;
    const float inv0 = 1.0f / l_run0;
    const float inv1 = 1.0f / l_run1;
    const int r0 = q0 + wid * 16 + (lane >> 2);
#pragma unroll
    for (int nf = 0; nf < 8; nf++) {
        const int d = nf * 8 + (lane & 3) * 2;
        uint32_t H, L;
        split2(o[nf][0] * inv0, o[nf][1] * inv0, H, L);
        size_t off = ((size_t)(b * SEQ + r0)) * CDIM + h * HDIM + d;
        *reinterpret_cast<uint32_t*>(g_ctx_hi + off) = H;
        *reinterpret_cast<uint32_t*>(g_ctx_lo + off) = L;
        split2(o[nf][2] * inv1, o[nf][3] * inv1, H, L);
        off = ((size_t)(b * SEQ + r0 + 8)) * CDIM + h * HDIM + d;
        *reinterpret_cast<uint32_t*>(g_ctx_hi + off) = H;
        *reinterpret_cast<uint32_t*>(g_ctx_lo + off) = L;
    }
}

// ---------------------------------------------------------------------------
// Launch
// ---------------------------------------------------------------------------
extern "C" void kernel_launch(void* const* d_in, const int* in_sizes, int n_in,
                              void* d_out, int out_size)
{
    const float* x      = (const float*)d_in[0];
    const float* w_qkv  = (const float*)d_in[1];
    const float* w_proj = (const float*)d_in[2];
    const float* b_proj = (const float*)d_in[3];
    float* out = (float*)d_out;
    (void)in_sizes; (void)n_in; (void)out_size;

    cudaFuncSetAttribute(qkv_mma,  cudaFuncAttributeMaxDynamicSharedMemorySize, GEMM_SMEM);
    cudaFuncSetAttribute(attn_mma, cudaFuncAttributeMaxDynamicSharedMemorySize, ATTN_SMEM);
    cudaFuncSetAttribute(proj_mma, cudaFuncAttributeMaxDynamicSharedMemorySize, GEMM_SMEM);

    __nv_bfloat16 *xh, *xl, *wh, *wl, *ph, *pl;
    cudaGetSymbolAddress((void**)&xh, g_x_hi);
    cudaGetSymbolAddress((void**)&xl, g_x_lo);
    cudaGetSymbolAddress((void**)&wh, g_wqkv_hi);
    cudaGetSymbolAddress((void**)&wl, g_wqkv_lo);
    cudaGetSymbolAddress((void**)&ph, g_wproj_hi);
    cudaGetSymbolAddress((void**)&pl, g_wproj_lo);

    convert_split<<<1024, 256>>>(x, xh, xl, MROWS * CDIM);
    convert_split<<<1024, 256>>>(w_qkv, wh, wl, QKV_N * CDIM);
    convert_split<<<512, 256>>>(w_proj, ph, pl, CDIM * CDIM);

    qkv_mma<<<dim3(QKV_N / 128, MROWS / 128), 256, GEMM_SMEM>>>();
    attn_mma<<<dim3(SEQ / 128, BH), 256, ATTN_SMEM>>>();
    proj_mma<<<dim3(CDIM / 128, MROWS / 128), 256, GEMM_SMEM>>>(b_proj, out);
}

// round 7
// speedup vs baseline: 2.8747x; 1.0247x over previous
#include <cuda_runtime.h>
#include <cuda_bf16.h>
#include <cstdint>

#define BATCH   2
#define SEQ     2048
#define CDIM    768
#define HEADS   12
#define HDIM    64
#define QKV_N   2304
#define MROWS   4096
#define BH      24
#define SCALEF  0.125f

// ---------------------------------------------------------------------------
// Scratch
// ---------------------------------------------------------------------------
__device__ __nv_bfloat16 g_x_hi[MROWS * CDIM];
__device__ __nv_bfloat16 g_x_lo[MROWS * CDIM];
__device__ __nv_bfloat16 g_wqkv_hi[QKV_N * CDIM];
__device__ __nv_bfloat16 g_wqkv_lo[QKV_N * CDIM];
__device__ __nv_bfloat16 g_wproj_hi[CDIM * CDIM];
__device__ __nv_bfloat16 g_wproj_lo[CDIM * CDIM];
__device__ __nv_bfloat16 g_q_hi[BH * SEQ * HDIM];    // [b,h,n,d], pre-scaled by 1/8
__device__ __nv_bfloat16 g_q_lo[BH * SEQ * HDIM];
__device__ __nv_bfloat16 g_k_hi[BH * SEQ * HDIM];
__device__ __nv_bfloat16 g_k_lo[BH * SEQ * HDIM];
__device__ __nv_bfloat16 g_vt_hi[BH * HDIM * SEQ];   // [b,h,d,n]
__device__ __nv_bfloat16 g_vt_lo[BH * HDIM * SEQ];
__device__ __nv_bfloat16 g_ctx_hi[MROWS * CDIM];
__device__ __nv_bfloat16 g_ctx_lo[MROWS * CDIM];

// ---------------------------------------------------------------------------
// Helpers (plain sm_80-era PTX: valid on compute_100 without 'a')
// ---------------------------------------------------------------------------
__device__ __forceinline__ uint32_t smem_u32(const void* p) {
    uint32_t a;
    asm("{ .reg .u64 t; cvta.to.shared.u64 t, %1; cvt.u32.u64 %0, t; }" : "=r"(a) : "l"(p));
    return a;
}
__device__ __forceinline__ void cp16(uint32_t dst, const void* src) {
    asm volatile("cp.async.cg.shared.global [%0], [%1], 16;" :: "r"(dst), "l"(src));
}
__device__ __forceinline__ void cp_commit() { asm volatile("cp.async.commit_group;"); }
template <int N> __device__ __forceinline__ void cp_wait() {
    asm volatile("cp.async.wait_group %0;" :: "n"(N));
}
__device__ __forceinline__ void ldsm4(uint32_t a, uint32_t& r0, uint32_t& r1, uint32_t& r2, uint32_t& r3) {
    asm volatile("ldmatrix.sync.aligned.m8n8.x4.shared.b16 {%0,%1,%2,%3}, [%4];"
                 : "=r"(r0), "=r"(r1), "=r"(r2), "=r"(r3) : "r"(a));
}
__device__ __forceinline__ void mma16816(float* c, const uint32_t* a, const uint32_t* b) {
    asm volatile("mma.sync.aligned.m16n8k16.row.col.f32.bf16.bf16.f32 "
                 "{%0,%1,%2,%3}, {%4,%5,%6,%7}, {%8,%9}, {%0,%1,%2,%3};"
                 : "+f"(c[0]), "+f"(c[1]), "+f"(c[2]), "+f"(c[3])
                 : "r"(a[0]), "r"(a[1]), "r"(a[2]), "r"(a[3]), "r"(b[0]), "r"(b[1]));
}
__device__ __forceinline__ void split2(float x, float y, uint32_t& hi, uint32_t& lo) {
    __nv_bfloat16 hx = __float2bfloat16_rn(x), hy = __float2bfloat16_rn(y);
    __nv_bfloat162 H; H.x = hx; H.y = hy;
    __nv_bfloat162 L;
    L.x = __float2bfloat16_rn(x - __bfloat162float(hx));
    L.y = __float2bfloat16_rn(y - __bfloat162float(hy));
    hi = *reinterpret_cast<uint32_t*>(&H);
    lo = *reinterpret_cast<uint32_t*>(&L);
}

// ---------------------------------------------------------------------------
// Convert fp32 -> split bf16
// ---------------------------------------------------------------------------
__global__ void convert_split(const float* __restrict__ src,
                              __nv_bfloat16* __restrict__ hi,
                              __nv_bfloat16* __restrict__ lo, int n)
{
    int i = blockIdx.x * blockDim.x + threadIdx.x;
    for (; i < n; i += gridDim.x * blockDim.x) {
        float v = src[i];
        __nv_bfloat16 h = __float2bfloat16_rn(v);
        hi[i] = h;
        lo[i] = __float2bfloat16_rn(v - __bfloat162float(h));
    }
}

// ---------------------------------------------------------------------------
// GEMM core: C(128x128) = (Ahi+Alo)(Bhi+Blo)^T over K=768. 256 threads.
// smem stage: [Ahi 10240][Alo 10240][Bhi 10240][Blo 10240], rows padded to 80B.
// One __syncthreads per K-iteration; rolling register fragment buffers.
// ---------------------------------------------------------------------------
#define GSTAGE   40960
#define G_ALO    10240
#define G_BHI    20480
#define G_BLO    30720
#define GEMM_SMEM (2 * GSTAGE)

__device__ __forceinline__ void gemm_load_stage(
    uint32_t sb, const __nv_bfloat16* Ahi, const __nv_bfloat16* Alo,
    const __nv_bfloat16* Bhi, const __nv_bfloat16* Blo,
    int m0, int n0, int k0, int tid)
{
    const int row = tid >> 1;
    const int cb  = (tid & 1) * 32;
    const size_t ga = (size_t)(m0 + row) * CDIM + k0;
    const size_t gb = (size_t)(n0 + row) * CDIM + k0;
    const uint32_t so = (uint32_t)row * 80 + cb;
    cp16(sb + so,               (const char*)(Ahi + ga) + cb);
    cp16(sb + so + 16,          (const char*)(Ahi + ga) + cb + 16);
    cp16(sb + G_ALO + so,       (const char*)(Alo + ga) + cb);
    cp16(sb + G_ALO + so + 16,  (const char*)(Alo + ga) + cb + 16);
    cp16(sb + G_BHI + so,       (const char*)(Bhi + gb) + cb);
    cp16(sb + G_BHI + so + 16,  (const char*)(Bhi + gb) + cb + 16);
    cp16(sb + G_BLO + so,       (const char*)(Blo + gb) + cb);
    cp16(sb + G_BLO + so + 16,  (const char*)(Blo + gb) + cb + 16);
}

__device__ __forceinline__ void ld_afrag(uint32_t st, int wm, int step,
                                         uint32_t a_lrow, uint32_t a_koff, uint32_t* a)
{
    const int ks = step >> 2, mf = step & 3;
    uint32_t addr = st + (uint32_t)(wm * 64 + mf * 16 + a_lrow) * 80 + ks * 32 + a_koff;
    ldsm4(addr,          a[0], a[1], a[2], a[3]);
    ldsm4(addr + G_ALO,  a[4], a[5], a[6], a[7]);
}

__device__ __forceinline__ void ld_bfrag(uint32_t st, int wn, int ks,
                                         uint32_t b_lrow, uint32_t b_koff,
                                         uint32_t bh[4][2], uint32_t bl[4][2])
{
#pragma unroll
    for (int nfp = 0; nfp < 2; nfp++) {
        uint32_t addr = st + G_BHI + (uint32_t)(wn * 32 + nfp * 16 + b_lrow) * 80 + ks * 32 + b_koff;
        ldsm4(addr, bh[2 * nfp][0], bh[2 * nfp][1], bh[2 * nfp + 1][0], bh[2 * nfp + 1][1]);
        ldsm4(addr + (G_BLO - G_BHI), bl[2 * nfp][0], bl[2 * nfp][1], bl[2 * nfp + 1][0], bl[2 * nfp + 1][1]);
    }
}

__device__ __forceinline__ void gemm_core(
    char* smem, const __nv_bfloat16* Ahi, const __nv_bfloat16* Alo,
    const __nv_bfloat16* Bhi, const __nv_bfloat16* Blo,
    int m0, int n0, float c[4][4][4])
{
    const int tid = threadIdx.x;
    const int lane = tid & 31;
    const int wid = tid >> 5;
    const int wm = wid >> 2, wn = wid & 3;
    const uint32_t sb = smem_u32(smem);

    const uint32_t a_lrow = lane % 16, a_koff = (lane >> 4) * 16;
    const uint32_t b_lrow = (lane % 8) + ((lane >> 4) << 3), b_koff = ((lane >> 3) & 1) * 16;

#pragma unroll
    for (int i = 0; i < 4; i++)
#pragma unroll
        for (int j = 0; j < 4; j++)
#pragma unroll
            for (int e = 0; e < 4; e++) c[i][j][e] = 0.0f;

    gemm_load_stage(sb, Ahi, Alo, Bhi, Blo, m0, n0, 0, tid);
    cp_commit();

    uint32_t ar[2][8];           // rolling A frag (hi+lo) per (ks,mf) step
    uint32_t bhr[2][4][2], blr[2][4][2];   // B frags per ks phase

    for (int it = 0; it < 24; it++) {
        cp_wait<0>();
        __syncthreads();
        if (it + 1 < 24) {
            gemm_load_stage(sb + ((it + 1) & 1) * GSTAGE, Ahi, Alo, Bhi, Blo,
                            m0, n0, (it + 1) * 32, tid);
            cp_commit();
        }
        const uint32_t st = sb + (it & 1) * GSTAGE;

        // preload B(ks=0) and A(step=0)
        ld_bfrag(st, wn, 0, b_lrow, b_koff, bhr[0], blr[0]);
        ld_afrag(st, wm, 0, a_lrow, a_koff, ar[0]);

#pragma unroll
        for (int ks = 0; ks < 2; ks++) {
            if (ks == 0)
                ld_bfrag(st, wn, 1, b_lrow, b_koff, bhr[1], blr[1]);
#pragma unroll
            for (int mf = 0; mf < 4; mf++) {
                const int step = ks * 4 + mf;
                if (step + 1 < 8)
                    ld_afrag(st, wm, step + 1, a_lrow, a_koff, ar[(step + 1) & 1]);
                const uint32_t* a = ar[step & 1];
#pragma unroll
                for (int nf = 0; nf < 4; nf++) {
                    mma16816(c[mf][nf], a,     bhr[ks][nf]);
                    mma16816(c[mf][nf], a,     blr[ks][nf]);
                    mma16816(c[mf][nf], a + 4, bhr[ks][nf]);
                }
            }
        }
    }
}

// ---------------------------------------------------------------------------
// QKV GEMM kernel: grid (2304/128=18, 4096/128=32), 256 threads, 2 CTAs/SM
// ---------------------------------------------------------------------------
__device__ __forceinline__ void qkv_store(int s, int rowg, int colg, float v0, float v1)
{
    const int b = rowg >> 11, n = rowg & 2047;
    const int rem = colg - s * CDIM;
    const int h = rem >> 6, d = rem & 63;
    if (s == 0) { v0 *= SCALEF; v1 *= SCALEF; }
    __nv_bfloat16 h0 = __float2bfloat16_rn(v0), h1 = __float2bfloat16_rn(v1);
    __nv_bfloat16 l0 = __float2bfloat16_rn(v0 - __bfloat162float(h0));
    __nv_bfloat16 l1 = __float2bfloat16_rn(v1 - __bfloat162float(h1));
    if (s == 2) {
        const size_t base = ((size_t)(b * HEADS + h) * HDIM) * SEQ;
        g_vt_hi[base + (size_t)d * SEQ + n]       = h0;
        g_vt_hi[base + (size_t)(d + 1) * SEQ + n] = h1;
        g_vt_lo[base + (size_t)d * SEQ + n]       = l0;
        g_vt_lo[base + (size_t)(d + 1) * SEQ + n] = l1;
    } else {
        const size_t off = ((size_t)(b * HEADS + h) * SEQ + n) * HDIM + d;
        __nv_bfloat16* dh = (s == 0) ? g_q_hi : g_k_hi;
        __nv_bfloat16* dl = (s == 0) ? g_q_lo : g_k_lo;
        __nv_bfloat162 H; H.x = h0; H.y = h1;
        __nv_bfloat162 L; L.x = l0; L.y = l1;
        *reinterpret_cast<__nv_bfloat162*>(dh + off) = H;
        *reinterpret_cast<__nv_bfloat162*>(dl + off) = L;
    }
}

__global__ __launch_bounds__(256, 2) void qkv_mma()
{
    extern __shared__ char smem[];
    const int n0 = blockIdx.x * 128;
    const int m0 = blockIdx.y * 128;
    const int lane = threadIdx.x & 31;
    const int wid = threadIdx.x >> 5;
    const int wm = wid >> 2, wn = wid & 3;

    float c[4][4][4];
    gemm_core(smem, g_x_hi, g_x_lo, g_wqkv_hi, g_wqkv_lo, m0, n0, c);

    const int s = n0 / CDIM;
#pragma unroll
    for (int mf = 0; mf < 4; mf++)
#pragma unroll
        for (int nf = 0; nf < 4; nf++) {
            const int rg = m0 + wm * 64 + mf * 16 + (lane >> 2);
            const int cg = n0 + wn * 32 + nf * 8 + (lane & 3) * 2;
            qkv_store(s, rg,     cg, c[mf][nf][0], c[mf][nf][1]);
            qkv_store(s, rg + 8, cg, c[mf][nf][2], c[mf][nf][3]);
        }
}

// ---------------------------------------------------------------------------
// Output projection kernel: grid (768/128=6, 4096/128=32), 2 CTAs/SM
// ---------------------------------------------------------------------------
__global__ __launch_bounds__(256, 2) void proj_mma(const float* __restrict__ bias,
                                                   float* __restrict__ out)
{
    extern __shared__ char smem[];
    const int n0 = blockIdx.x * 128;
    const int m0 = blockIdx.y * 128;
    const int lane = threadIdx.x & 31;
    const int wid = threadIdx.x >> 5;
    const int wm = wid >> 2, wn = wid & 3;

    float c[4][4][4];
    gemm_core(smem, g_ctx_hi, g_ctx_lo, g_wproj_hi, g_wproj_lo, m0, n0, c);

#pragma unroll
    for (int mf = 0; mf < 4; mf++)
#pragma unroll
        for (int nf = 0; nf < 4; nf++) {
            const int rg = m0 + wm * 64 + mf * 16 + (lane >> 2);
            const int cg = n0 + wn * 32 + nf * 8 + (lane & 3) * 2;
            const float b0 = bias[cg], b1 = bias[cg + 1];
            float2 v0 = make_float2(c[mf][nf][0] + b0, c[mf][nf][1] + b1);
            float2 v1 = make_float2(c[mf][nf][2] + b0, c[mf][nf][3] + b1);
            *reinterpret_cast<float2*>(out + (size_t)rg * CDIM + cg) = v0;
            *reinterpret_cast<float2*>(out + (size_t)(rg + 8) * CDIM + cg) = v1;
        }
}

// ---------------------------------------------------------------------------
// Flash attention (warp-MMA, FA2-style). grid (SEQ/128=16, BH=24), 256 threads.
// Warp w owns q-rows [16w, 16w+16). S and P live in registers only. 2 CTAs/SM.
// One __syncthreads per kv iteration.
// smem: Qhi 18432 | Qlo 18432 | 2 stages x [Khi 9216|Klo 9216|Vthi 9216|Vtlo 9216]
// ---------------------------------------------------------------------------
#define AQ_LO    18432
#define AKV      36864
#define ASTAGE   36864
#define AK_LO    9216
#define AV_HI    18432
#define AV_LO    27648
#define ATTN_SMEM (AKV + 2 * ASTAGE)   // 110592

__device__ __forceinline__ void attn_load_stage(
    uint32_t sb, const __nv_bfloat16* Kh, const __nv_bfloat16* Kl,
    const __nv_bfloat16* Vh, const __nv_bfloat16* Vl, int kv0, int tid)
{
    const int row = tid >> 2;                 // 0..63
    const int cb  = (tid & 3) * 32;           // byte offset in 128B row
    const uint32_t so = (uint32_t)row * 144 + cb;
    const char* kh = (const char*)(Kh + (size_t)(kv0 + row) * HDIM) + cb;
    const char* kl = (const char*)(Kl + (size_t)(kv0 + row) * HDIM) + cb;
    const char* vh = (const char*)(Vh + (size_t)row * SEQ + kv0) + cb;
    const char* vl = (const char*)(Vl + (size_t)row * SEQ + kv0) + cb;
    cp16(sb + so, kh);            cp16(sb + so + 16, kh + 16);
    cp16(sb + AK_LO + so, kl);    cp16(sb + AK_LO + so + 16, kl + 16);
    cp16(sb + AV_HI + so, vh);    cp16(sb + AV_HI + so + 16, vh + 16);
    cp16(sb + AV_LO + so, vl);    cp16(sb + AV_LO + so + 16, vl + 16);
}

__global__ __launch_bounds__(256, 2) void attn_mma()
{
    extern __shared__ char smem[];
    const uint32_t sb = smem_u32(smem);
    const int q0 = blockIdx.x * 128;
    const int bh = blockIdx.y;
    const int tid = threadIdx.x;
    const int lane = tid & 31;
    const int wid = tid >> 5;

    const __nv_bfloat16* Qh = g_q_hi + (size_t)bh * SEQ * HDIM;
    const __nv_bfloat16* Ql = g_q_lo + (size_t)bh * SEQ * HDIM;
    const __nv_bfloat16* Kh = g_k_hi + (size_t)bh * SEQ * HDIM;
    const __nv_bfloat16* Kl = g_k_lo + (size_t)bh * SEQ * HDIM;
    const __nv_bfloat16* Vh = g_vt_hi + (size_t)bh * HDIM * SEQ;
    const __nv_bfloat16* Vl = g_vt_lo + (size_t)bh * HDIM * SEQ;

    // Load Q tile into smem (rows padded to 144B)
    {
        const int row = tid >> 1;
        const int cb = (tid & 1) * 64;
        const uint4* qs = reinterpret_cast<const uint4*>((const char*)(Qh + (size_t)(q0 + row) * HDIM) + cb);
        const uint4* ql = reinterpret_cast<const uint4*>((const char*)(Ql + (size_t)(q0 + row) * HDIM) + cb);
        uint4* dh = reinterpret_cast<uint4*>(smem + (uint32_t)row * 144 + cb);
        uint4* dl = reinterpret_cast<uint4*>(smem + AQ_LO + (uint32_t)row * 144 + cb);
#pragma unroll
        for (int i = 0; i < 4; i++) { dh[i] = qs[i]; dl[i] = ql[i]; }
    }
    // Prefetch first KV stage
    attn_load_stage(sb + AKV, Kh, Kl, Vh, Vl, 0, tid);
    cp_commit();
    __syncthreads();

    const uint32_t a_lrow = lane % 16, a_koff = (lane >> 4) * 16;
    const uint32_t b_lrow = (lane % 8) + ((lane >> 4) << 3), b_koff = ((lane >> 3) & 1) * 16;

    // Hoist Q fragments (constant across kv tiles)
    uint32_t qh[4][4], qlr[4][4];
#pragma unroll
    for (int ks = 0; ks < 4; ks++) {
        uint32_t addr = sb + (uint32_t)(wid * 16 + a_lrow) * 144 + ks * 32 + a_koff;
        ldsm4(addr, qh[ks][0], qh[ks][1], qh[ks][2], qh[ks][3]);
        ldsm4(addr + AQ_LO, qlr[ks][0], qlr[ks][1], qlr[ks][2], qlr[ks][3]);
    }

    float o[8][4];
#pragma unroll
    for (int nf = 0; nf < 8; nf++)
#pragma unroll
        for (int e = 0; e < 4; e++) o[nf][e] = 0.0f;
    float m_run0 = -1e30f, m_run1 = -1e30f, l_run0 = 0.0f, l_run1 = 0.0f;

    for (int it = 0; it < SEQ / 64; it++) {
        cp_wait<0>();
        __syncthreads();
        if (it + 1 < SEQ / 64) {
            attn_load_stage(sb + AKV + ((it + 1) & 1) * ASTAGE, Kh, Kl, Vh, Vl, (it + 1) * 64, tid);
            cp_commit();
        }
        const uint32_t st = sb + AKV + (it & 1) * ASTAGE;

        // ---- S = Q K^T (3-pass split) ----
        float s[8][4];
#pragma unroll
        for (int nf = 0; nf < 8; nf++)
#pragma unroll
            for (int e = 0; e < 4; e++) s[nf][e] = 0.0f;
#pragma unroll
        for (int ks = 0; ks < 4; ks++) {
            uint32_t kbh[8][2], kbl[8][2];
#pragma unroll
            for (int nfp = 0; nfp < 4; nfp++) {
                uint32_t addr = st + (uint32_t)(nfp * 16 + b_lrow) * 144 + ks * 32 + b_koff;
                ldsm4(addr, kbh[2 * nfp][0], kbh[2 * nfp][1], kbh[2 * nfp + 1][0], kbh[2 * nfp + 1][1]);
                ldsm4(addr + AK_LO, kbl[2 * nfp][0], kbl[2 * nfp][1], kbl[2 * nfp + 1][0], kbl[2 * nfp + 1][1]);
            }
#pragma unroll
            for (int nf = 0; nf < 8; nf++) {
                mma16816(s[nf], qh[ks], kbh[nf]);
                mma16816(s[nf], qh[ks], kbl[nf]);
                mma16816(s[nf], qlr[ks], kbh[nf]);
            }
        }

        // ---- online softmax (rows l/4 and l/4+8; reduce over 4-lane group) ----
        float vm0 = -1e30f, vm1 = -1e30f;
#pragma unroll
        for (int nf = 0; nf < 8; nf++) {
            vm0 = fmaxf(vm0, fmaxf(s[nf][0], s[nf][1]));
            vm1 = fmaxf(vm1, fmaxf(s[nf][2], s[nf][3]));
        }
        vm0 = fmaxf(vm0, __shfl_xor_sync(0xffffffff, vm0, 1));
        vm0 = fmaxf(vm0, __shfl_xor_sync(0xffffffff, vm0, 2));
        vm1 = fmaxf(vm1, __shfl_xor_sync(0xffffffff, vm1, 1));
        vm1 = fmaxf(vm1, __shfl_xor_sync(0xffffffff, vm1, 2));
        const float nm0 = fmaxf(m_run0, vm0);
        const float nm1 = fmaxf(m_run1, vm1);
        const float corr0 = __expf(m_run0 - nm0);
        const float corr1 = __expf(m_run1 - nm1);
        float sum0 = 0.0f, sum1 = 0.0f;
#pragma unroll
        for (int nf = 0; nf < 8; nf++) {
            s[nf][0] = __expf(s[nf][0] - nm0); sum0 += s[nf][0];
            s[nf][1] = __expf(s[nf][1] - nm0); sum0 += s[nf][1];
            s[nf][2] = __expf(s[nf][2] - nm1); sum1 += s[nf][2];
            s[nf][3] = __expf(s[nf][3] - nm1); sum1 += s[nf][3];
        }
        sum0 += __shfl_xor_sync(0xffffffff, sum0, 1);
        sum0 += __shfl_xor_sync(0xffffffff, sum0, 2);
        sum1 += __shfl_xor_sync(0xffffffff, sum1, 1);
        sum1 += __shfl_xor_sync(0xffffffff, sum1, 2);
        l_run0 = l_run0 * corr0 + sum0;
        l_run1 = l_run1 * corr1 + sum1;
        m_run0 = nm0; m_run1 = nm1;
#pragma unroll
        for (int nf = 0; nf < 8; nf++) {
            o[nf][0] *= corr0; o[nf][1] *= corr0;
            o[nf][2] *= corr1; o[nf][3] *= corr1;
        }

        // ---- O += P V (P repacked in registers as A-frags, split hi/lo) ----
#pragma unroll
        for (int ks2 = 0; ks2 < 4; ks2++) {
            uint32_t pah[4], pal[4];
            split2(s[2 * ks2][0],     s[2 * ks2][1],     pah[0], pal[0]);
            split2(s[2 * ks2][2],     s[2 * ks2][3],     pah[1], pal[1]);
            split2(s[2 * ks2 + 1][0], s[2 * ks2 + 1][1], pah[2], pal[2]);
            split2(s[2 * ks2 + 1][2], s[2 * ks2 + 1][3], pah[3], pal[3]);
            uint32_t vbh[8][2], vbl[8][2];
#pragma unroll
            for (int nfp = 0; nfp < 4; nfp++) {
                uint32_t addr = st + AV_HI + (uint32_t)(nfp * 16 + b_lrow) * 144 + ks2 * 32 + b_koff;
                ldsm4(addr, vbh[2 * nfp][0], vbh[2 * nfp][1], vbh[2 * nfp + 1][0], vbh[2 * nfp + 1][1]);
                ldsm4(addr + (AV_LO - AV_HI), vbl[2 * nfp][0], vbl[2 * nfp][1], vbl[2 * nfp + 1][0], vbl[2 * nfp + 1][1]);
            }
#pragma unroll
            for (int nf = 0; nf < 8; nf++) {
                mma16816(o[nf], pah, vbh[nf]);
                mma16816(o[nf], pah, vbl[nf]);
                mma16816(o[nf], pal, vbh[nf]);
            }
        }
    }

    // ---- epilogue: normalize, split, write ctx ----
    const int b = bh / HEADS;
    const int h = bh % HEADS;
    const float inv0 = 1.0f / l_run0;
    const float inv1 = 1.0f / l_run1;
    const int r0 = q0 + wid * 16 + (lane >> 2);
#pragma unroll
    for (int nf = 0; nf < 8; nf++) {
        const int d = nf * 8 + (lane & 3) * 2;
        uint32_t H, L;
        split2(o[nf][0] * inv0, o[nf][1] * inv0, H, L);
        size_t off = ((size_t)(b * SEQ + r0)) * CDIM + h * HDIM + d;
        *reinterpret_cast<uint32_t*>(g_ctx_hi + off) = H;
        *reinterpret_cast<uint32_t*>(g_ctx_lo + off) = L;
        split2(o[nf][2] * inv1, o[nf][3] * inv1, H, L);
        off = ((size_t)(b * SEQ + r0 + 8)) * CDIM + h * HDIM + d;
        *reinterpret_cast<uint32_t*>(g_ctx_hi + off) = H;
        *reinterpret_cast<uint32_t*>(g_ctx_lo + off) = L;
    }
}

// ---------------------------------------------------------------------------
// Launch
// ---------------------------------------------------------------------------
extern "C" void kernel_launch(void* const* d_in, const int* in_sizes, int n_in,
                              void* d_out, int out_size)
{
    const float* x      = (const float*)d_in[0];
    const float* w_qkv  = (const float*)d_in[1];
    const float* w_proj = (const float*)d_in[2];
    const float* b_proj = (const float*)d_in[3];
    float* out = (float*)d_out;
    (void)in_sizes; (void)n_in; (void)out_size;

    cudaFuncSetAttribute(qkv_mma,  cudaFuncAttributeMaxDynamicSharedMemorySize, GEMM_SMEM);
    cudaFuncSetAttribute(attn_mma, cudaFuncAttributeMaxDynamicSharedMemorySize, ATTN_SMEM);
    cudaFuncSetAttribute(proj_mma, cudaFuncAttributeMaxDynamicSharedMemorySize, GEMM_SMEM);

    __nv_bfloat16 *xh, *xl, *wh, *wl, *ph, *pl;
    cudaGetSymbolAddress((void**)&xh, g_x_hi);
    cudaGetSymbolAddress((void**)&xl, g_x_lo);
    cudaGetSymbolAddress((void**)&wh, g_wqkv_hi);
    cudaGetSymbolAddress((void**)&wl, g_wqkv_lo);
    cudaGetSymbolAddress((void**)&ph, g_wproj_hi);
    cudaGetSymbolAddress((void**)&pl, g_wproj_lo);

    convert_split<<<1024, 256>>>(x, xh, xl, MROWS * CDIM);
    convert_split<<<1024, 256>>>(w_qkv, wh, wl, QKV_N * CDIM);
    convert_split<<<512, 256>>>(w_proj, ph, pl, CDIM * CDIM);

    qkv_mma<<<dim3(QKV_N / 128, MROWS / 128), 256, GEMM_SMEM>>>();
    attn_mma<<<dim3(SEQ / 128, BH), 256, ATTN_SMEM>>>();
    proj_mma<<<dim3(CDIM / 128, MROWS / 128), 256, GEMM_SMEM>>>(b_proj, out);
}